// round 2
// baseline (speedup 1.0000x reference)
#include <cuda_runtime.h>
#include <cstdint>
#include <cstddef>

// ---------------------------------------------------------------------------
// 2-layer GCN: out = GCNConv2( relu( GCNConv1(x) ) )
// GCNConv: deg[v] = 1 + sum_{e:dst=v} w[e]; dinv = rsqrt(deg)
//          norm[e] = dinv[src]*w*dinv[dst];  self-loop norm = dinv[v]^2
//          h = x @ W;  out[v] = sum_{e:dst=v} norm[e]*h[src[e]] + dinv[v]^2*h[v] + b
// edge_index dtype is auto-detected (int32 vs int64) on device.
// ---------------------------------------------------------------------------

#define N_MAX 100000
#define E_MAX 1200000

// Scratch (allocation-free rule: __device__ globals). 256B aligned for float4/red.v4.
__device__ __align__(256) float g_deg [N_MAX];
__device__ __align__(256) float g_dinv[N_MAX];
__device__ __align__(256) int   g_src [E_MAX];
__device__ __align__(256) int   g_dst [E_MAX];
__device__ __align__(256) float g_norm[E_MAX];
__device__ __align__(256) float g_h1  [(size_t)N_MAX * 64];
__device__ __align__(256) float g_agg1[(size_t)N_MAX * 64];
__device__ __align__(256) float g_h2  [(size_t)N_MAX * 32];
__device__ int g_is32;   // 1 if edge_index is int32, 0 if int64

// ---------------------------------------------------------------------------
__global__ void init_deg_kernel(int n) {
    int i = blockIdx.x * blockDim.x + threadIdx.x;
    if (i < n) g_deg[i] = 1.0f;                  // self-loop weight
    if (i == 0) g_is32 = 0;
}

// Detect dtype: read buffer as int64; any value outside [0,n) => data is int32.
__global__ void detect_kernel(const long long* __restrict__ ei64, int e2, int n) {
    int i = blockIdx.x * blockDim.x + threadIdx.x;
    int bad = 0;
    if (i < e2) {
        long long v = ei64[i];
        bad = ((unsigned long long)v >= (unsigned long long)n) ? 1 : 0;
    }
    unsigned m = __ballot_sync(0xFFFFFFFFu, bad);
    if (m && (threadIdx.x & 31) == (__ffs(m) - 1))
        atomicOr(&g_is32, 1);
}

// Decode indices per detected dtype, clamp defensively, accumulate in-degree.
__global__ void edge_prep_kernel(const void* __restrict__ ei,
                                 const float* __restrict__ ew, int e, int n) {
    int i = blockIdx.x * blockDim.x + threadIdx.x;
    if (i >= e) return;
    int s, d;
    if (g_is32) {
        const int* p = (const int*)ei;
        s = p[i];
        d = p[(size_t)e + i];
    } else {
        const long long* p = (const long long*)ei;
        s = (int)p[i];
        d = (int)p[(size_t)e + i];
    }
    if ((unsigned)s >= (unsigned)n) s = 0;   // never triggers on valid data
    if ((unsigned)d >= (unsigned)n) d = 0;
    g_src[i] = s;
    g_dst[i] = d;
    atomicAdd(&g_deg[d], ew[i]);
}

__global__ void dinv_kernel(int n) {
    int i = blockIdx.x * blockDim.x + threadIdx.x;
    if (i < n) {
        float dg = g_deg[i];
        g_dinv[i] = (dg > 0.0f) ? rsqrtf(dg) : 0.0f;
    }
}

__global__ void norm_kernel(const float* __restrict__ ew, int e) {
    int i = blockIdx.x * blockDim.x + threadIdx.x;
    if (i >= e) return;
    g_norm[i] = g_dinv[g_src[i]] * ew[i] * g_dinv[g_dst[i]];
}

// ---------------------------------------------------------------------------
// GEMM:  H[n, COUT] = f(X) @ W   (CIN = 64)
//  LAYER 1: X = external x, H=g_h1, AGG=g_agg1 seeded with dinv^2*h (self loop)
//  LAYER 2: X = relu(g_agg1 + b1), H=g_h2, AGG=out seeded with dinv^2*h + b2
// Block: 32 rows; thread tile 4 rows x 4 cols; (COUT/4)*8 threads.
// ---------------------------------------------------------------------------
template<int LAYER>
__global__ __launch_bounds__(128)
void gemm_fused_kernel(const float* __restrict__ Xext,
                       const float* __restrict__ Wm,
                       const float* __restrict__ bin,
                       const float* __restrict__ bout,
                       float* __restrict__ AGGext,
                       int n) {
    constexpr int  COUT    = (LAYER == 1) ? 64 : 32;
    constexpr bool RELU_IN = (LAYER == 2);
    constexpr int  CIN  = 64;
    constexpr int  ROWS = 32;
    constexpr int  CG   = COUT / 4;      // column groups
    constexpr int  NT   = CG * 8;        // threads (8 row groups of 4 rows)
    constexpr int  XPAD = 68;            // 16B-aligned, conflict-skewed row pitch

    const float* X   = (LAYER == 1) ? Xext : g_agg1;
    float*       H   = (LAYER == 1) ? g_h1 : g_h2;
    float*       AGG = (LAYER == 1) ? g_agg1 : AGGext;

    __shared__ float Ws[CIN * COUT];
    __shared__ float xs[ROWS * XPAD];

    const int tid  = threadIdx.x;
    const int row0 = blockIdx.x * ROWS;

    // Load W (row-major [CIN][COUT]) via float4
    for (int i = tid * 4; i < CIN * COUT; i += NT * 4)
        *(float4*)(Ws + i) = *(const float4*)(Wm + i);

    // Load 32 input rows via float4 (+ optional bias-relu transform)
    for (int i = tid; i < ROWS * (CIN / 4); i += NT) {
        int r  = i >> 4;          // CIN/4 == 16
        int c4 = i & 15;
        int gr = row0 + r;
        float4 v = make_float4(0.f, 0.f, 0.f, 0.f);
        if (gr < n) {
            v = *(const float4*)(X + (size_t)gr * CIN + c4 * 4);
            if (RELU_IN) {
                float4 b = *(const float4*)(bin + c4 * 4);
                v.x = fmaxf(v.x + b.x, 0.f);
                v.y = fmaxf(v.y + b.y, 0.f);
                v.z = fmaxf(v.z + b.z, 0.f);
                v.w = fmaxf(v.w + b.w, 0.f);
            }
        }
        *(float4*)(xs + r * XPAD + c4 * 4) = v;
    }
    __syncthreads();

    const int jg = tid % CG;
    const int rg = tid / CG;
    const int j0 = jg * 4;
    const int r0 = rg * 4;

    float acc[4][4] = {};
#pragma unroll
    for (int k = 0; k < CIN; ++k) {
        float4 w = *(const float4*)(Ws + k * COUT + j0);
        float x0 = xs[(r0 + 0) * XPAD + k];
        float x1 = xs[(r0 + 1) * XPAD + k];
        float x2 = xs[(r0 + 2) * XPAD + k];
        float x3 = xs[(r0 + 3) * XPAD + k];
        acc[0][0] += x0 * w.x; acc[0][1] += x0 * w.y; acc[0][2] += x0 * w.z; acc[0][3] += x0 * w.w;
        acc[1][0] += x1 * w.x; acc[1][1] += x1 * w.y; acc[1][2] += x1 * w.z; acc[1][3] += x1 * w.w;
        acc[2][0] += x2 * w.x; acc[2][1] += x2 * w.y; acc[2][2] += x2 * w.z; acc[2][3] += x2 * w.w;
        acc[3][0] += x3 * w.x; acc[3][1] += x3 * w.y; acc[3][2] += x3 * w.z; acc[3][3] += x3 * w.w;
    }

#pragma unroll
    for (int r = 0; r < 4; ++r) {
        int gr = row0 + r0 + r;
        if (gr >= n) continue;
        float dv  = g_dinv[gr];
        float dv2 = dv * dv;
        float4 h = make_float4(acc[r][0], acc[r][1], acc[r][2], acc[r][3]);
        *(float4*)(H + (size_t)gr * COUT + j0) = h;
        float4 a = make_float4(dv2 * h.x, dv2 * h.y, dv2 * h.z, dv2 * h.w);
        if (LAYER == 2) {
            float4 b = *(const float4*)(bout + j0);
            a.x += b.x; a.y += b.y; a.z += b.z; a.w += b.w;
        }
        *(float4*)(AGG + (size_t)gr * COUT + j0) = a;
    }
}

// ---------------------------------------------------------------------------
// Edge scatter: AGG[dst] += norm * H[src], float4 chunks, vector reduction.
// C4 consecutive threads handle one edge -> 256B/128B coalesced gather+atomic.
// ---------------------------------------------------------------------------
__device__ __forceinline__ void red_add_f32x4(float4* addr, float4 v) {
    asm volatile("red.global.add.v4.f32 [%0], {%1, %2, %3, %4};"
                 :: "l"(addr), "f"(v.x), "f"(v.y), "f"(v.z), "f"(v.w)
                 : "memory");
}

template<int LAYER>
__global__ __launch_bounds__(256)
void scatter_kernel(float4* __restrict__ AGGext, int e) {
    constexpr int C4 = (LAYER == 1) ? 16 : 8;   // COUT/4
    const float4* H   = (const float4*)((LAYER == 1) ? g_h1 : g_h2);
    float4*       AGG = (LAYER == 1) ? (float4*)g_agg1 : AGGext;

    long long i = (long long)blockIdx.x * blockDim.x + threadIdx.x;
    long long ee = i / C4;
    int c = (int)(i % C4);
    if (ee >= e) return;
    int   s  = g_src[ee];
    int   d  = g_dst[ee];
    float nm = g_norm[ee];
    float4 v = H[(size_t)s * C4 + c];
    float4 a = make_float4(v.x * nm, v.y * nm, v.z * nm, v.w * nm);
    red_add_f32x4(&AGG[(size_t)d * C4 + c], a);
}

// ---------------------------------------------------------------------------
extern "C" void kernel_launch(void* const* d_in, const int* in_sizes, int n_in,
                              void* d_out, int out_size) {
    const float* x   = (const float*)d_in[0];   // [n, 64]
    const void*  ei  = d_in[1];                 // [2, e] int32 or int64
    const float* ew  = (const float*)d_in[2];   // [e]
    const float* W1  = (const float*)d_in[3];   // [64, 64]
    const float* b1  = (const float*)d_in[4];   // [64]
    const float* W2  = (const float*)d_in[5];   // [64, 32]
    const float* b2  = (const float*)d_in[6];   // [32]
    float*       out = (float*)d_out;           // [n, 32]

    const int n = in_sizes[0] / 64;
    const int e = in_sizes[2];

    const int T = 256;
    const int nb_n = (n + T - 1) / T;
    const int nb_e = (e + T - 1) / T;
    const int gemm_blocks = (n + 31) / 32;

    // 1. dtype detect + degree / normalization prep
    init_deg_kernel<<<nb_n, T>>>(n);
    detect_kernel<<<nb_e, T>>>((const long long*)ei, e, n);
    edge_prep_kernel<<<nb_e, T>>>(ei, ew, e, n);
    dinv_kernel<<<nb_n, T>>>(n);
    norm_kernel<<<nb_e, T>>>(ew, e);

    // 2. layer 1: h1 = x@W1 ; agg1 seeded with dinv^2*h1 (self loop)
    gemm_fused_kernel<1><<<gemm_blocks, 128>>>(x, W1, nullptr, nullptr, nullptr, n);

    // 3. layer-1 edge aggregation: agg1[dst] += norm*h1[src]
    {
        long long tot = (long long)e * 16;
        int blocks = (int)((tot + T - 1) / T);
        scatter_kernel<1><<<blocks, T>>>(nullptr, e);
    }

    // 4. layer 2: x2 = relu(agg1+b1); h2 = x2@W2 ; out seeded with dinv^2*h2+b2
    gemm_fused_kernel<2><<<gemm_blocks, 64>>>(nullptr, W2, b1, b2, out, n);

    // 5. layer-2 edge aggregation directly into d_out
    {
        long long tot = (long long)e * 8;
        int blocks = (int)((tot + T - 1) / T);
        scatter_kernel<2><<<blocks, T>>>((float4*)out, e);
    }
}

// round 3
// speedup vs baseline: 1.1572x; 1.1572x over previous
#include <cuda_runtime.h>
#include <cstdint>
#include <cstddef>

// ---------------------------------------------------------------------------
// 2-layer GCN, CSR-sorted aggregation (no feature atomics), f32x2 GEMMs.
// out[v] = sum_{e: dst=v} norm[e]*h[src] + dinv[v]^2*h[v] (+bias)
// ---------------------------------------------------------------------------

#define N_MAX 100000
#define E_MAX 1200000

__device__ __align__(256) float g_deg  [N_MAX];
__device__ __align__(256) int   g_cnt  [N_MAX];
__device__ __align__(256) float g_dinv [N_MAX];
__device__ __align__(256) int   g_ptr  [N_MAX + 1];
__device__ __align__(256) int   g_fill [N_MAX];
__device__ __align__(256) int   g_src  [E_MAX];
__device__ __align__(256) int   g_dst  [E_MAX];
__device__ __align__(256) int   g_srcs [E_MAX];   // dst-sorted src
__device__ __align__(256) float g_norms[E_MAX];   // dst-sorted norm
__device__ __align__(256) float g_h1  [(size_t)N_MAX * 64];
__device__ __align__(256) float g_agg1[(size_t)N_MAX * 64];
__device__ __align__(256) float g_h2  [(size_t)N_MAX * 32];
__device__ __align__(256) int   g_bsum[128];
__device__ __align__(256) int   g_boff[128];
__device__ int g_is32;

// ---------------------------------------------------------------------------
__global__ void init_kernel(int n) {
    int i = blockIdx.x * blockDim.x + threadIdx.x;
    if (i < n) { g_deg[i] = 1.0f; g_cnt[i] = 0; }
    if (i == 0) g_is32 = 0;
}

// Read buffer as int64; any value outside [0,n) => data is int32.
__global__ void detect_kernel(const long long* __restrict__ ei64, int e, int n) {
    int i = blockIdx.x * blockDim.x + threadIdx.x;
    int bad = 0;
    if (i < e) {
        long long v = ei64[i];
        bad = ((unsigned long long)v >= (unsigned long long)n) ? 1 : 0;
    }
    unsigned m = __ballot_sync(0xFFFFFFFFu, bad);
    if (m && (threadIdx.x & 31) == (__ffs(m) - 1)) atomicOr(&g_is32, 1);
}

__global__ void edge_prep_kernel(const void* __restrict__ ei,
                                 const float* __restrict__ ew, int e, int n) {
    int i = blockIdx.x * blockDim.x + threadIdx.x;
    if (i >= e) return;
    int s, d;
    if (g_is32) {
        const int* p = (const int*)ei;
        s = p[i]; d = p[(size_t)e + i];
    } else {
        const long long* p = (const long long*)ei;
        s = (int)p[i]; d = (int)p[(size_t)e + i];
    }
    if ((unsigned)s >= (unsigned)n) s = 0;
    if ((unsigned)d >= (unsigned)n) d = 0;
    g_src[i] = s;
    g_dst[i] = d;
    atomicAdd(&g_deg[d], ew[i]);
    atomicAdd(&g_cnt[d], 1);
}

__global__ void dinv_kernel(int n) {
    int i = blockIdx.x * blockDim.x + threadIdx.x;
    if (i < n) {
        float dg = g_deg[i];
        g_dinv[i] = (dg > 0.0f) ? rsqrtf(dg) : 0.0f;
    }
}

// ---------------- exclusive scan of g_cnt -> g_ptr (3 kernels) -------------
__global__ void scan1_kernel(int n) {             // 256 thr, 1024 elems/block
    __shared__ int wsum[8];
    int b = blockIdx.x, t = threadIdx.x;
    int base = b * 1024 + t * 4;
    int c[4];
#pragma unroll
    for (int j = 0; j < 4; j++) { int idx = base + j; c[j] = (idx < n) ? g_cnt[idx] : 0; }
    int tsum = c[0] + c[1] + c[2] + c[3];
    int lane = t & 31, w = t >> 5;
    int v = tsum;
#pragma unroll
    for (int off = 1; off < 32; off <<= 1) {
        int u = __shfl_up_sync(~0u, v, off); if (lane >= off) v += u;
    }
    if (lane == 31) wsum[w] = v;
    __syncthreads();
    if (w == 0) {
        int s = (lane < 8) ? wsum[lane] : 0;
#pragma unroll
        for (int off = 1; off < 8; off <<= 1) {
            int u = __shfl_up_sync(~0u, s, off); if (lane >= off) s += u;
        }
        if (lane < 8) wsum[lane] = s;
    }
    __syncthreads();
    int excl = v - tsum + ((w > 0) ? wsum[w - 1] : 0);
    int run = excl;
#pragma unroll
    for (int j = 0; j < 4; j++) { int idx = base + j; if (idx < n) g_ptr[idx] = run; run += c[j]; }
    if (t == 255) g_bsum[b] = excl + tsum;        // block total
}

__global__ void scan2_kernel(int nb) {            // single block, 128 thr
    __shared__ int sh[4];
    int t = threadIdx.x;
    int v = (t < nb) ? g_bsum[t] : 0;
    int lane = t & 31, w = t >> 5;
    int s = v;
#pragma unroll
    for (int off = 1; off < 32; off <<= 1) {
        int u = __shfl_up_sync(~0u, s, off); if (lane >= off) s += u;
    }
    if (lane == 31) sh[w] = s;
    __syncthreads();
    if (w == 0) {
        int x = (lane < 4) ? sh[lane] : 0;
#pragma unroll
        for (int off = 1; off < 4; off <<= 1) {
            int u = __shfl_up_sync(~0u, x, off); if (lane >= off) x += u;
        }
        if (lane < 4) sh[lane] = x;
    }
    __syncthreads();
    int excl = s - v + ((w > 0) ? sh[w - 1] : 0);
    if (t < nb) g_boff[t] = excl;
}

__global__ void scan3_kernel(int n, int e) {
    int i = blockIdx.x * blockDim.x + threadIdx.x;
    if (i < n) {
        int p = g_ptr[i] + g_boff[i >> 10];
        g_ptr[i] = p;
        g_fill[i] = p;
    }
    if (i == 0) g_ptr[n] = e;
}

// fill sorted arrays; fuses norm computation
__global__ void fill_kernel(const float* __restrict__ ew, int e) {
    int i = blockIdx.x * blockDim.x + threadIdx.x;
    if (i >= e) return;
    int s = g_src[i], d = g_dst[i];
    float nm = g_dinv[s] * ew[i] * g_dinv[d];
    int pos = atomicAdd(&g_fill[d], 1);
    g_srcs[pos] = s;
    g_norms[pos] = nm;
}

// ---------------------------------------------------------------------------
// GEMM: H = f(X) @ W  (CIN=64) with packed f32x2 FFMA.
// LAYER 1: X=x ext, COUT=64, ROWS=32. LAYER 2: X=relu(g_agg1+b1), COUT=32, ROWS=64.
// ---------------------------------------------------------------------------
typedef unsigned long long u64t;
__device__ __forceinline__ u64t pack2(float lo, float hi) {
    u64t r; asm("mov.b64 %0, {%1, %2};" : "=l"(r) : "f"(lo), "f"(hi)); return r;
}
__device__ __forceinline__ void ffma2(u64t& d, u64t a, u64t b) {
    asm("fma.rn.f32x2 %0, %1, %2, %0;" : "+l"(d) : "l"(a), "l"(b));
}
__device__ __forceinline__ float2 unpack2(u64t v) {
    float2 f; asm("mov.b64 {%0, %1}, %2;" : "=f"(f.x), "=f"(f.y) : "l"(v)); return f;
}

template<int LAYER>
__global__ __launch_bounds__(128)
void gemm_kernel(const float* __restrict__ Xext,
                 const float* __restrict__ Wm,
                 const float* __restrict__ bin, int n) {
    constexpr int COUT = (LAYER == 1) ? 64 : 32;
    constexpr int ROWS = (LAYER == 1) ? 32 : 64;
    constexpr int CIN  = 64;
    constexpr int CG   = COUT / 4;
    constexpr int NT   = 128;            // CG * (ROWS/4)
    constexpr int XPAD = 68;

    const float* X = (LAYER == 1) ? Xext : g_agg1;
    float*       H = (LAYER == 1) ? g_h1 : g_h2;

    __shared__ float Ws[CIN * COUT];
    __shared__ float xs[ROWS * XPAD];

    const int tid  = threadIdx.x;
    const int row0 = blockIdx.x * ROWS;

    for (int i = tid * 4; i < CIN * COUT; i += NT * 4)
        *(float4*)(Ws + i) = *(const float4*)(Wm + i);

    for (int i = tid; i < ROWS * (CIN / 4); i += NT) {
        int r  = i >> 4;
        int c4 = i & 15;
        int gr = row0 + r;
        float4 v = make_float4(0.f, 0.f, 0.f, 0.f);
        if (gr < n) {
            v = *(const float4*)(X + (size_t)gr * CIN + c4 * 4);
            if (LAYER == 2) {
                float4 b = *(const float4*)(bin + c4 * 4);
                v.x = fmaxf(v.x + b.x, 0.f);
                v.y = fmaxf(v.y + b.y, 0.f);
                v.z = fmaxf(v.z + b.z, 0.f);
                v.w = fmaxf(v.w + b.w, 0.f);
            }
        }
        *(float4*)(xs + r * XPAD + c4 * 4) = v;
    }
    __syncthreads();

    const int jg = tid % CG;
    const int rg = tid / CG;
    const int j0 = jg * 4;
    const int r0 = rg * 4;

    u64t acc[4][2] = {};
#pragma unroll
    for (int k = 0; k < CIN; ++k) {
        const u64t* wp = (const u64t*)(Ws + k * COUT + j0);
        u64t w01 = wp[0];
        u64t w23 = wp[1];
#pragma unroll
        for (int r = 0; r < 4; ++r) {
            float xv = xs[(r0 + r) * XPAD + k];
            u64t xx = pack2(xv, xv);
            ffma2(acc[r][0], xx, w01);
            ffma2(acc[r][1], xx, w23);
        }
    }

#pragma unroll
    for (int r = 0; r < 4; ++r) {
        int gr = row0 + r0 + r;
        if (gr >= n) continue;
        float2 a0 = unpack2(acc[r][0]);
        float2 a1 = unpack2(acc[r][1]);
        *(float4*)(H + (size_t)gr * COUT + j0) =
            make_float4(a0.x, a0.y, a1.x, a1.y);
    }
}

// ---------------------------------------------------------------------------
// CSR aggregation: C4 threads per dst accumulate over its edge range, add
// self-loop (dinv^2 * h[v]) and bias (layer 2), single streaming write.
// ---------------------------------------------------------------------------
template<int LAYER>
__global__ __launch_bounds__(256)
void csr_agg_kernel(const float* __restrict__ bias, float* __restrict__ AGGext, int n) {
    constexpr int C4 = (LAYER == 1) ? 16 : 8;
    const float4* __restrict__ H = (const float4*)((LAYER == 1) ? g_h1 : g_h2);
    float4* AGG = (LAYER == 1) ? (float4*)g_agg1 : (float4*)AGGext;

    int gi = blockIdx.x * blockDim.x + threadIdx.x;
    int v = gi / C4;
    int c = gi % C4;
    if (v >= n) return;

    int p0 = g_ptr[v], p1 = g_ptr[v + 1];

    float4 acc0 = make_float4(0.f, 0.f, 0.f, 0.f);
    float4 acc1 = make_float4(0.f, 0.f, 0.f, 0.f);
    int k = p0;
    for (; k + 1 < p1; k += 2) {
        int   s0 = g_srcs[k],     s1 = g_srcs[k + 1];
        float n0 = g_norms[k],    n1 = g_norms[k + 1];
        float4 h0 = __ldg(&H[(size_t)s0 * C4 + c]);
        float4 h1 = __ldg(&H[(size_t)s1 * C4 + c]);
        acc0.x += n0 * h0.x; acc0.y += n0 * h0.y; acc0.z += n0 * h0.z; acc0.w += n0 * h0.w;
        acc1.x += n1 * h1.x; acc1.y += n1 * h1.y; acc1.z += n1 * h1.z; acc1.w += n1 * h1.w;
    }
    if (k < p1) {
        int   s0 = g_srcs[k];
        float n0 = g_norms[k];
        float4 h0 = __ldg(&H[(size_t)s0 * C4 + c]);
        acc0.x += n0 * h0.x; acc0.y += n0 * h0.y; acc0.z += n0 * h0.z; acc0.w += n0 * h0.w;
    }

    float dv  = g_dinv[v];
    float dv2 = dv * dv;
    float4 hv = __ldg(&H[(size_t)v * C4 + c]);
    float4 r;
    r.x = acc0.x + acc1.x + dv2 * hv.x;
    r.y = acc0.y + acc1.y + dv2 * hv.y;
    r.z = acc0.z + acc1.z + dv2 * hv.z;
    r.w = acc0.w + acc1.w + dv2 * hv.w;
    if (LAYER == 2) {
        float4 b = ((const float4*)bias)[c];
        r.x += b.x; r.y += b.y; r.z += b.z; r.w += b.w;
    }
    AGG[(size_t)v * C4 + c] = r;
}

// ---------------------------------------------------------------------------
extern "C" void kernel_launch(void* const* d_in, const int* in_sizes, int n_in,
                              void* d_out, int out_size) {
    const float* x   = (const float*)d_in[0];
    const void*  ei  = d_in[1];
    const float* ew  = (const float*)d_in[2];
    const float* W1  = (const float*)d_in[3];
    const float* b1  = (const float*)d_in[4];
    const float* W2  = (const float*)d_in[5];
    const float* b2  = (const float*)d_in[6];
    float*       out = (float*)d_out;

    const int n = in_sizes[0] / 64;
    const int e = in_sizes[2];

    const int T = 256;
    const int nb_n = (n + T - 1) / T;
    const int nb_e = (e + T - 1) / T;
    const int nscan = (n + 1023) / 1024;

    init_kernel<<<nb_n, T>>>(n);
    detect_kernel<<<nb_e, T>>>((const long long*)ei, e, n);
    edge_prep_kernel<<<nb_e, T>>>(ei, ew, e, n);
    dinv_kernel<<<nb_n, T>>>(n);
    scan1_kernel<<<nscan, 256>>>(n);
    scan2_kernel<<<1, 128>>>(nscan);
    scan3_kernel<<<nb_n, T>>>(n, e);
    fill_kernel<<<nb_e, T>>>(ew, e);

    gemm_kernel<1><<<(n + 31) / 32, 128>>>(x, W1, nullptr, n);
    csr_agg_kernel<1><<<(n * 16 + T - 1) / T, T>>>(nullptr, nullptr, n);
    gemm_kernel<2><<<(n + 63) / 64, 128>>>(nullptr, W2, b1, n);
    csr_agg_kernel<2><<<(n * 8 + T - 1) / T, T>>>(b2, out, n);
}